// round 15
// baseline (speedup 1.0000x reference)
#include <cuda_runtime.h>
#include <cuda_fp16.h>
#include <cstdint>

// ============================ helpers ============================
__device__ __forceinline__ float tf32rnd(float x) {
    uint32_t o; asm("cvt.rna.tf32.f32 %0, %1;" : "=r"(o) : "f"(x)); return __uint_as_float(o);
}
__device__ __forceinline__ uint32_t smem_u32(const void* p) {
    uint32_t a;
    asm("{ .reg .u64 t; cvta.to.shared.u64 t, %1; cvt.u32.u64 %0, t; }" : "=r"(a) : "l"(p));
    return a;
}
#define LDSM_X4(r0, r1, r2, r3, addr) \
    asm volatile("ldmatrix.sync.aligned.m8n8.x4.shared.b16 {%0,%1,%2,%3}, [%4];" \
                 : "=r"(r0), "=r"(r1), "=r"(r2), "=r"(r3) : "r"(addr))
#define MMA_TF32(d, a0, a1, a2, a3, b0, b1) \
    asm volatile("mma.sync.aligned.m16n8k8.row.col.f32.tf32.tf32.f32 " \
                 "{%0,%1,%2,%3},{%4,%5,%6,%7},{%8,%9},{%0,%1,%2,%3};" \
                 : "+f"(d[0]), "+f"(d[1]), "+f"(d[2]), "+f"(d[3]) \
                 : "r"(a0), "r"(a1), "r"(a2), "r"(a3), "r"(b0), "r"(b1))

// ============================ scratch ============================
#define MAXN 100000
#define MAXE 1000000
__device__ float g_dinv[MAXN];
__device__ int   g_cnt[MAXN];
__device__ int   g_rowstart[MAXN + 1];
__device__ int   g_cursor[MAXN];
__device__ int   g_blksum[1024];
__device__ int   g_csrsrc[MAXE];
__device__ float g_csrcoef[MAXE];
__device__ float g_xa[(size_t)MAXN * 128];
__device__ float g_h1[(size_t)MAXN * 256];
__device__ float g_t [(size_t)MAXN * 128];
__device__ float g_z [(size_t)MAXN * 128];
__device__ float g_bnsum[256];
__device__ float g_bnsumsq[256];
__device__ float g_bnsc[256];
__device__ float g_bnsh[256];
__device__ float g_w1t_hi[256 * 128];
__device__ float g_w1t_lo[256 * 128];
__device__ float g_w2t_hi[128 * 256];
__device__ float g_w2t_lo[128 * 256];
__device__ float g_w3t_hi[128 * 128];
__device__ float g_w3t_lo[128 * 128];

// ============================ CSR build ============================
__global__ void hist_kernel(int* __restrict__ cnt, const int* __restrict__ dst, int E) {
    int i = blockIdx.x * blockDim.x + threadIdx.x;
    if (i < E) atomicAdd(&cnt[dst[i]], 1);
}
__global__ void dinv_kernel(const int* __restrict__ cnt, float* __restrict__ dinv, int N) {
    int i = blockIdx.x * blockDim.x + threadIdx.x;
    if (i < N) dinv[i] = rsqrtf((float)cnt[i] + 1.0f);
}
__global__ void ps1_kernel(const int* __restrict__ cnt, int* __restrict__ excl,
                           int* __restrict__ blksum, int N) {
    __shared__ int wsum[8];
    int t = threadIdx.x;
    int i = blockIdx.x * 256 + t;
    int v = (i < N) ? cnt[i] : 0;
    int lane = t & 31, wid = t >> 5;
    int x = v;
    #pragma unroll
    for (int o = 1; o < 32; o <<= 1) {
        int y = __shfl_up_sync(0xffffffffu, x, o);
        if (lane >= o) x += y;
    }
    if (lane == 31) wsum[wid] = x;
    __syncthreads();
    if (t == 0) {
        int run = 0;
        #pragma unroll
        for (int w = 0; w < 8; w++) { int tmp = wsum[w]; wsum[w] = run; run += tmp; }
        blksum[blockIdx.x] = run;
    }
    __syncthreads();
    if (i < N) excl[i] = x - v + wsum[wid];
}
__global__ void ps2_kernel(int* __restrict__ blksum, int nb) {
    __shared__ int wsum[16];
    int t = threadIdx.x;
    int v = (t < nb) ? blksum[t] : 0;
    int lane = t & 31, wid = t >> 5;
    int x = v;
    #pragma unroll
    for (int o = 1; o < 32; o <<= 1) {
        int y = __shfl_up_sync(0xffffffffu, x, o);
        if (lane >= o) x += y;
    }
    if (lane == 31) wsum[wid] = x;
    __syncthreads();
    if (t == 0) {
        int run = 0;
        #pragma unroll
        for (int w = 0; w < 16; w++) { int tmp = wsum[w]; wsum[w] = run; run += tmp; }
    }
    __syncthreads();
    if (t < nb) blksum[t] = x - v + wsum[wid];
}
__global__ void ps3_kernel(int* __restrict__ excl, const int* __restrict__ blksum,
                           int* __restrict__ cursor, int N, int E) {
    int i = blockIdx.x * 256 + threadIdx.x;
    if (i < N) {
        int v = excl[i] + blksum[blockIdx.x];
        excl[i] = v;
        cursor[i] = v;
    }
    if (i == 0) excl[N] = E;
}
__global__ void scatter_kernel(const int* __restrict__ src, const int* __restrict__ dst,
                               int* __restrict__ cursor, int* __restrict__ csrc,
                               float* __restrict__ ccoef, const float* __restrict__ dinv, int E) {
    int e = blockIdx.x * blockDim.x + threadIdx.x;
    if (e >= E) return;
    int s = src[e], d = dst[e];
    int pos = atomicAdd(&cursor[d], 1);
    csrc[pos]  = s;
    ccoef[pos] = dinv[s] * dinv[d];
}

// ============================ fused CSR aggregation ============================
template<bool FLN>
__global__ void agg_csr_kernel(const float* __restrict__ feat, float* __restrict__ out,
                               const int* __restrict__ rowstart, const int* __restrict__ csrc,
                               const float* __restrict__ ccoef, const float* __restrict__ dinv,
                               int N, const float* __restrict__ b2,
                               const float* __restrict__ lng, const float* __restrict__ lnb) {
    int w = (blockIdx.x * blockDim.x + threadIdx.x) >> 5;
    int lane = threadIdx.x & 31;
    if (w >= N) return;
    int beg = rowstart[w], end = rowstart[w + 1];
    float4 a0 = make_float4(0.f, 0.f, 0.f, 0.f);
    float4 a1 = make_float4(0.f, 0.f, 0.f, 0.f);
    int idx = beg;
    for (; idx + 1 < end; idx += 2) {
        int s0 = __ldg(&csrc[idx]), s1 = __ldg(&csrc[idx + 1]);
        float c0 = __ldg(&ccoef[idx]), c1 = __ldg(&ccoef[idx + 1]);
        float4 f0 = *(const float4*)(feat + (size_t)s0 * 128 + lane * 4);
        float4 f1 = *(const float4*)(feat + (size_t)s1 * 128 + lane * 4);
        a0.x = fmaf(f0.x, c0, a0.x); a0.y = fmaf(f0.y, c0, a0.y);
        a0.z = fmaf(f0.z, c0, a0.z); a0.w = fmaf(f0.w, c0, a0.w);
        a1.x = fmaf(f1.x, c1, a1.x); a1.y = fmaf(f1.y, c1, a1.y);
        a1.z = fmaf(f1.z, c1, a1.z); a1.w = fmaf(f1.w, c1, a1.w);
    }
    if (idx < end) {
        int s0 = __ldg(&csrc[idx]);
        float c0 = __ldg(&ccoef[idx]);
        float4 f0 = *(const float4*)(feat + (size_t)s0 * 128 + lane * 4);
        a0.x = fmaf(f0.x, c0, a0.x); a0.y = fmaf(f0.y, c0, a0.y);
        a0.z = fmaf(f0.z, c0, a0.z); a0.w = fmaf(f0.w, c0, a0.w);
    }
    float di = dinv[w];
    float c2 = di * di;
    float4 fs = *(const float4*)(feat + (size_t)w * 128 + lane * 4);
    float4 v;
    v.x = fmaf(fs.x, c2, a0.x + a1.x);
    v.y = fmaf(fs.y, c2, a0.y + a1.y);
    v.z = fmaf(fs.z, c2, a0.z + a1.z);
    v.w = fmaf(fs.w, c2, a0.w + a1.w);
    size_t base = (size_t)w * 128 + lane * 4;
    if (!FLN) {
        *(float4*)(out + base) = v;
        return;
    }
    float4 bb = *(const float4*)(b2 + lane * 4);
    v.x += bb.x; v.y += bb.y; v.z += bb.z; v.w += bb.w;
    float s = v.x + v.y + v.z + v.w;
    #pragma unroll
    for (int off = 16; off; off >>= 1) s += __shfl_xor_sync(0xffffffffu, s, off);
    float mu = s * (1.0f / 128.0f);
    float dx = v.x - mu, dy = v.y - mu, dz = v.z - mu, dw = v.w - mu;
    float q = dx * dx + dy * dy + dz * dz + dw * dw;
    #pragma unroll
    for (int off = 16; off; off >>= 1) q += __shfl_xor_sync(0xffffffffu, q, off);
    float rs = rsqrtf(q * (1.0f / 128.0f) + 1e-5f);
    float4 g = *(const float4*)(lng + lane * 4);
    float4 bo = *(const float4*)(lnb + lane * 4);
    float4 o;
    o.x = fmaxf(fmaf(dx * rs, g.x, bo.x), 0.f);
    o.y = fmaxf(fmaf(dy * rs, g.y, bo.y), 0.f);
    o.z = fmaxf(fmaf(dz * rs, g.z, bo.z), 0.f);
    o.w = fmaxf(fmaf(dw * rs, g.w, bo.w), 0.f);
    *(float4*)(out + base) = o;
}

// ============================ misc kernels ============================
__global__ void wsplit_kernel(const float* __restrict__ W, float* __restrict__ hiT,
                              float* __restrict__ loT, int K, int NOUT) {
    int i = blockIdx.x * blockDim.x + threadIdx.x;
    if (i >= K * NOUT) return;
    int k = i / NOUT, n = i % NOUT;
    float x = W[i];
    float h = tf32rnd(x);
    float l = tf32rnd(x - h);
    hiT[(size_t)n * K + k] = h;
    loT[(size_t)n * K + k] = l;
}
__global__ void bnfinal_kernel(const float* __restrict__ sum, const float* __restrict__ sumsq,
                               const float* __restrict__ gamma, const float* __restrict__ beta,
                               float* __restrict__ sc, float* __restrict__ sh, int N) {
    int c = threadIdx.x;
    float invN = 1.0f / (float)N;
    float mu = sum[c] * invN;
    float var = fmaxf(sumsq[c] * invN - mu * mu, 0.f);
    float scv = gamma[c] * rsqrtf(var + 1e-5f);
    sc[c] = scv;
    sh[c] = beta[c] - mu * scv;
}
__global__ void decode_kernel(const float* __restrict__ z, const int* __restrict__ ia,
                              const int* __restrict__ ib,
                              const float* __restrict__ cutoff, float* __restrict__ out,
                              int EL, int writeRound) {
    int w = (blockIdx.x * blockDim.x + threadIdx.x) >> 5;
    int lane = threadIdx.x & 31;
    if (w >= EL) return;
    int a = ia[w];
    int b = ib[w];
    float4 za = *(const float4*)(z + (size_t)a * 128 + lane * 4);
    float4 zb = *(const float4*)(z + (size_t)b * 128 + lane * 4);
    float s = za.x * zb.x + za.y * zb.y + za.z * zb.z + za.w * zb.w;
    #pragma unroll
    for (int off = 16; off; off >>= 1) s += __shfl_xor_sync(0xffffffffu, s, off);
    if (lane == 0) {
        out[w] = s;
        if (writeRound) out[(size_t)EL + w] = (s < cutoff[0]) ? 0.0f : 1.0f;
    }
}

// ============================ mma.sync tf32x3 GEMM (R12 main loop) ============================
// STATS: accumulate per-column sum/sumsq of output into gsum/gsq (BatchNorm),
// epilogue-only registers (occupancy-neutral).
template<int K, bool FUSE, bool HASBIAS, bool STATS>
__global__ void __launch_bounds__(256, 2)
mm_gemm_kernel(const float* __restrict__ A,
               const float* __restrict__ BTh, const float* __restrict__ BTl,
               const float* __restrict__ bias,
               const float* __restrict__ sc, const float* __restrict__ sh,
               float* __restrict__ C, int Nrows, int ldC,
               float* __restrict__ gsum, float* __restrict__ gsq) {
    constexpr int NC  = K / 32;
    constexpr int PAD = 36;
    constexpr int ASZ = 128 * PAD * 4;

    extern __shared__ char smem[];
    float* sAh = (float*)(smem);
    float* sAl = (float*)(smem + ASZ);
    float* sBh = (float*)(smem + 2 * ASZ);
    float* sBl = (float*)(smem + 3 * ASZ);

    int tid = threadIdx.x, lane = tid & 31, warp = tid >> 5;
    int warpM = warp & 1, warpN = warp >> 1;
    int rowBase  = blockIdx.x * 128;
    int colBaseG = blockIdx.y * 128;

    float acc[4][4][4];
    #pragma unroll
    for (int i = 0; i < 4; i++)
        #pragma unroll
        for (int j = 0; j < 4; j++)
            #pragma unroll
            for (int r = 0; r < 4; r++) acc[i][j][r] = 0.f;

    int larow  = tid >> 1;
    int lkhalf = (tid & 1) * 16;
    bool rOK = (rowBase + larow) < Nrows;
    const float* aRow  = A   + (size_t)(rowBase + larow) * K + lkhalf;
    const float* bRowH = BTh + (size_t)(colBaseG + larow) * K + lkhalf;
    const float* bRowL = BTl + (size_t)(colBaseG + larow) * K + lkhalf;
    float* sAhp = sAh + larow * PAD + lkhalf;
    float* sAlp = sAl + larow * PAD + lkhalf;
    float* sBhp = sBh + larow * PAD + lkhalf;
    float* sBlp = sBl + larow * PAD + lkhalf;

    int al_r = (lane & 7) + (lane & 8);
    int al_k = (lane & 16) >> 2;
    uint32_t aHbase = smem_u32(sAh) + (uint32_t)(((warpM * 64 + al_r) * PAD + al_k) << 2);
    uint32_t aLbase = aHbase + ASZ;
    int bl_n = (lane & 7) + ((lane & 16) >> 1);
    int bl_k = (lane & 8) >> 1;
    uint32_t bHbase = smem_u32(sBh) + (uint32_t)(((warpN * 32 + bl_n) * PAD + bl_k) << 2);
    uint32_t bLbase = bHbase + ASZ;

    for (int c = 0; c < NC; c++) {
        int k0 = c * 32;
        __syncthreads();
        {
            const float4* ap = (const float4*)(aRow + k0);
            #pragma unroll
            for (int j = 0; j < 4; j++) {
                float4 v = rOK ? ap[j] : make_float4(0.f, 0.f, 0.f, 0.f);
                if (FUSE) {
                    int kg = k0 + lkhalf + j * 4;
                    float4 s4 = *(const float4*)(sc + kg);
                    float4 h4 = *(const float4*)(sh + kg);
                    v.x = fmaxf(fmaf(v.x, s4.x, h4.x), 0.f);
                    v.y = fmaxf(fmaf(v.y, s4.y, h4.y), 0.f);
                    v.z = fmaxf(fmaf(v.z, s4.z, h4.z), 0.f);
                    v.w = fmaxf(fmaf(v.w, s4.w, h4.w), 0.f);
                }
                float4 hi, lo;
                hi.x = tf32rnd(v.x); lo.x = tf32rnd(v.x - hi.x);
                hi.y = tf32rnd(v.y); lo.y = tf32rnd(v.y - hi.y);
                hi.z = tf32rnd(v.z); lo.z = tf32rnd(v.z - hi.z);
                hi.w = tf32rnd(v.w); lo.w = tf32rnd(v.w - hi.w);
                *(float4*)(sAhp + j * 4) = hi;
                *(float4*)(sAlp + j * 4) = lo;
            }
        }
        {
            const float4* bh = (const float4*)(bRowH + k0);
            const float4* bl = (const float4*)(bRowL + k0);
            #pragma unroll
            for (int j = 0; j < 4; j++) *(float4*)(sBhp + j * 4) = bh[j];
            #pragma unroll
            for (int j = 0; j < 4; j++) *(float4*)(sBlp + j * 4) = bl[j];
        }
        __syncthreads();

        #pragma unroll
        for (int s = 0; s < 4; s++) {
            uint32_t koff = (uint32_t)(s * 8 * 4);
            uint32_t bh[2][4], bl[2][4];
            #pragma unroll
            for (int p = 0; p < 2; p++) {
                uint32_t po = (uint32_t)(p * 16 * PAD * 4);
                LDSM_X4(bh[p][0], bh[p][1], bh[p][2], bh[p][3], bHbase + po + koff);
                LDSM_X4(bl[p][0], bl[p][1], bl[p][2], bl[p][3], bLbase + po + koff);
            }
            #pragma unroll
            for (int i = 0; i < 4; i++) {
                uint32_t io = (uint32_t)(i * 16 * PAD * 4);
                uint32_t ah0, ah1, ah2, ah3, alo0, alo1, alo2, alo3;
                LDSM_X4(ah0, ah1, ah2, ah3, aHbase + io + koff);
                LDSM_X4(alo0, alo1, alo2, alo3, aLbase + io + koff);
                #pragma unroll
                for (int j = 0; j < 4; j++) {
                    int p = j >> 1, o = (j & 1) * 2;
                    MMA_TF32(acc[i][j], ah0, ah1, ah2, ah3, bh[p][o], bh[p][o + 1]);
                    MMA_TF32(acc[i][j], ah0, ah1, ah2, ah3, bl[p][o], bl[p][o + 1]);
                    MMA_TF32(acc[i][j], alo0, alo1, alo2, alo3, bh[p][o], bh[p][o + 1]);
                }
            }
        }
    }

    // ---- epilogue (+ optional fused BN column stats; epilogue-only registers)
    int gid = lane >> 2, tc2 = (lane & 3) * 2;
    float cs[8], cq[8];
    if (STATS) {
        #pragma unroll
        for (int j = 0; j < 8; j++) { cs[j] = 0.f; cq[j] = 0.f; }
    }
    #pragma unroll
    for (int i = 0; i < 4; i++) {
        int r0 = rowBase + warpM * 64 + i * 16 + gid;
        int r1 = r0 + 8;
        #pragma unroll
        for (int j = 0; j < 4; j++) {
            int col = colBaseG + warpN * 32 + j * 8 + tc2;
            float bx = 0.f, by = 0.f;
            if (HASBIAS) { bx = bias[col]; by = bias[col + 1]; }
            float v0 = acc[i][j][0] + bx, v1 = acc[i][j][1] + by;
            float v2 = acc[i][j][2] + bx, v3 = acc[i][j][3] + by;
            if (r0 < Nrows) {
                *(float2*)(C + (size_t)r0 * ldC + col) = make_float2(v0, v1);
                if (STATS) {
                    cs[j * 2] += v0; cq[j * 2] = fmaf(v0, v0, cq[j * 2]);
                    cs[j * 2 + 1] += v1; cq[j * 2 + 1] = fmaf(v1, v1, cq[j * 2 + 1]);
                }
            }
            if (r1 < Nrows) {
                *(float2*)(C + (size_t)r1 * ldC + col) = make_float2(v2, v3);
                if (STATS) {
                    cs[j * 2] += v2; cq[j * 2] = fmaf(v2, v2, cq[j * 2]);
                    cs[j * 2 + 1] += v3; cq[j * 2 + 1] = fmaf(v3, v3, cq[j * 2 + 1]);
                }
            }
        }
    }
    if (STATS) {
        #pragma unroll
        for (int o = 4; o <= 16; o <<= 1) {
            #pragma unroll
            for (int j = 0; j < 8; j++) {
                cs[j] += __shfl_xor_sync(0xffffffffu, cs[j], o);
                cq[j] += __shfl_xor_sync(0xffffffffu, cq[j], o);
            }
        }
        if (lane < 4) {
            #pragma unroll
            for (int j = 0; j < 4; j++) {
                int col = colBaseG + warpN * 32 + j * 8 + lane * 2;
                atomicAdd(&gsum[col],     cs[j * 2]);
                atomicAdd(&gsum[col + 1], cs[j * 2 + 1]);
                atomicAdd(&gsq[col],      cq[j * 2]);
                atomicAdd(&gsq[col + 1],  cq[j * 2 + 1]);
            }
        }
    }
}

// ============================ launch ============================
extern "C" void kernel_launch(void* const* d_in, const int* in_sizes, int n_in,
                              void* d_out, int out_size) {
    const float* x    = (const float*)d_in[0];
    const int*   ei   = (const int*)d_in[1];
    const int*   eli  = (const int*)d_in[2];
    const float* cut  = (const float*)d_in[3];
    const float* W1   = (const float*)d_in[4];
    const float* b1   = (const float*)d_in[5];
    const float* bng  = (const float*)d_in[6];
    const float* bnb  = (const float*)d_in[7];
    const float* W2   = (const float*)d_in[8];
    const float* b2   = (const float*)d_in[9];
    const float* lng  = (const float*)d_in[10];
    const float* lnb  = (const float*)d_in[11];
    const float* linW = (const float*)d_in[12];
    const float* linb = (const float*)d_in[13];

    int N  = in_sizes[0] / 128;
    int E  = in_sizes[1] / 2;
    int EL = in_sizes[2] / 2;
    const int* src = ei;
    const int* dst = ei + E;
    const int* la  = eli;
    const int* lb  = eli + EL;
    float* out = (float*)d_out;

    void* p;
    float *dinv, *xa, *h1, *t, *z, *bsum, *bsq, *bsc, *bsh, *ccoef;
    float *w1h, *w1l, *w2h, *w2l, *w3h, *w3l;
    int *cnt, *rowstart, *cursor, *blksum, *csrc;
    cudaGetSymbolAddress(&p, g_dinv);     dinv = (float*)p;
    cudaGetSymbolAddress(&p, g_cnt);      cnt  = (int*)p;
    cudaGetSymbolAddress(&p, g_rowstart); rowstart = (int*)p;
    cudaGetSymbolAddress(&p, g_cursor);   cursor = (int*)p;
    cudaGetSymbolAddress(&p, g_blksum);   blksum = (int*)p;
    cudaGetSymbolAddress(&p, g_csrsrc);   csrc  = (int*)p;
    cudaGetSymbolAddress(&p, g_csrcoef);  ccoef = (float*)p;
    cudaGetSymbolAddress(&p, g_xa);       xa   = (float*)p;
    cudaGetSymbolAddress(&p, g_h1);       h1   = (float*)p;
    cudaGetSymbolAddress(&p, g_t);        t    = (float*)p;
    cudaGetSymbolAddress(&p, g_z);        z    = (float*)p;
    cudaGetSymbolAddress(&p, g_bnsum);    bsum = (float*)p;
    cudaGetSymbolAddress(&p, g_bnsumsq);  bsq  = (float*)p;
    cudaGetSymbolAddress(&p, g_bnsc);     bsc  = (float*)p;
    cudaGetSymbolAddress(&p, g_bnsh);     bsh  = (float*)p;
    cudaGetSymbolAddress(&p, g_w1t_hi);   w1h  = (float*)p;
    cudaGetSymbolAddress(&p, g_w1t_lo);   w1l  = (float*)p;
    cudaGetSymbolAddress(&p, g_w2t_hi);   w2h  = (float*)p;
    cudaGetSymbolAddress(&p, g_w2t_lo);   w2l  = (float*)p;
    cudaGetSymbolAddress(&p, g_w3t_hi);   w3h  = (float*)p;
    cudaGetSymbolAddress(&p, g_w3t_lo);   w3l  = (float*)p;

    constexpr int SMEMSZ = 4 * 128 * 36 * 4;  // 73728 B, 2 CTAs/SM
    cudaFuncSetAttribute(mm_gemm_kernel<128, false, true, true>,
                         cudaFuncAttributeMaxDynamicSharedMemorySize, SMEMSZ);
    cudaFuncSetAttribute(mm_gemm_kernel<256, true, false, false>,
                         cudaFuncAttributeMaxDynamicSharedMemorySize, SMEMSZ);
    cudaFuncSetAttribute(mm_gemm_kernel<128, false, true, false>,
                         cudaFuncAttributeMaxDynamicSharedMemorySize, SMEMSZ);

    cudaMemsetAsync(cnt,  0, (size_t)N * sizeof(int));
    cudaMemsetAsync(bsum, 0, 256 * sizeof(float));
    cudaMemsetAsync(bsq,  0, 256 * sizeof(float));

    wsplit_kernel<<<(128 * 256 + 255) / 256, 256>>>(W1, w1h, w1l, 128, 256);
    wsplit_kernel<<<(256 * 128 + 255) / 256, 256>>>(W2, w2h, w2l, 256, 128);
    wsplit_kernel<<<(128 * 128 + 255) / 256, 256>>>(linW, w3h, w3l, 128, 128);

    // ---- CSR build
    int nb = (N + 255) / 256;
    hist_kernel<<<(E + 255) / 256, 256>>>(cnt, dst, E);
    dinv_kernel<<<nb, 256>>>(cnt, dinv, N);
    ps1_kernel<<<nb, 256>>>(cnt, rowstart, blksum, N);
    ps2_kernel<<<1, 512>>>(blksum, nb);
    ps3_kernel<<<nb, 256>>>(rowstart, blksum, cursor, N, E);
    scatter_kernel<<<(E + 255) / 256, 256>>>(src, dst, cursor, csrc, ccoef, dinv, E);

    int tiles = (N + 127) / 128;
    int aggblocks = (N + 7) / 8;

    // layer 1: CSR aggregate -> xa, GEMM1 (+b1, fused BN stats)
    agg_csr_kernel<false><<<aggblocks, 256>>>(x, xa, rowstart, csrc, ccoef, dinv, N,
                                              nullptr, nullptr, nullptr);
    mm_gemm_kernel<128, false, true, true><<<dim3(tiles, 2), 256, SMEMSZ>>>(
        xa, w1h, w1l, b1, nullptr, nullptr, h1, N, 256, bsum, bsq);

    bnfinal_kernel<<<1, 256>>>(bsum, bsq, bng, bnb, bsc, bsh, N);

    // layer 2: GEMM2 (fused BN+ReLU on A) -> t, CSR aggregate + b2 + LN + ReLU -> xa
    mm_gemm_kernel<256, true, false, false><<<dim3(tiles, 1), 256, SMEMSZ>>>(
        h1, w2h, w2l, nullptr, bsc, bsh, t, N, 128, nullptr, nullptr);
    agg_csr_kernel<true><<<aggblocks, 256>>>(t, xa, rowstart, csrc, ccoef, dinv, N,
                                             b2, lng, lnb);

    // final linear (+linb)
    mm_gemm_kernel<128, false, true, false><<<dim3(tiles, 1), 256, SMEMSZ>>>(
        xa, w3h, w3l, linb, nullptr, nullptr, z, N, 128, nullptr, nullptr);

    // decode
    int writeRound = (out_size >= 2 * EL) ? 1 : 0;
    decode_kernel<<<((size_t)EL + 7) / 8, 256>>>(z, la, lb, cut, out, EL, writeRound);
}

// round 16
// speedup vs baseline: 1.2613x; 1.2613x over previous
#include <cuda_runtime.h>
#include <cuda_fp16.h>
#include <cstdint>

// ============================ helpers ============================
__device__ __forceinline__ float tf32rnd(float x) {
    uint32_t o; asm("cvt.rna.tf32.f32 %0, %1;" : "=r"(o) : "f"(x)); return __uint_as_float(o);
}
__device__ __forceinline__ uint32_t smem_u32(const void* p) {
    uint32_t a;
    asm("{ .reg .u64 t; cvta.to.shared.u64 t, %1; cvt.u32.u64 %0, t; }" : "=r"(a) : "l"(p));
    return a;
}
#define LDSM_X4(r0, r1, r2, r3, addr) \
    asm volatile("ldmatrix.sync.aligned.m8n8.x4.shared.b16 {%0,%1,%2,%3}, [%4];" \
                 : "=r"(r0), "=r"(r1), "=r"(r2), "=r"(r3) : "r"(addr))
#define MMA_TF32(d, a0, a1, a2, a3, b0, b1) \
    asm volatile("mma.sync.aligned.m16n8k8.row.col.f32.tf32.tf32.f32 " \
                 "{%0,%1,%2,%3},{%4,%5,%6,%7},{%8,%9},{%0,%1,%2,%3};" \
                 : "+f"(d[0]), "+f"(d[1]), "+f"(d[2]), "+f"(d[3]) \
                 : "r"(a0), "r"(a1), "r"(a2), "r"(a3), "r"(b0), "r"(b1))

// ============================ scratch ============================
#define MAXN 100000
#define MAXE 1000000
__device__ float g_dinv[MAXN];
__device__ int   g_cnt[MAXN];
__device__ int   g_rowstart[MAXN + 1];
__device__ int   g_cursor[MAXN];
__device__ int   g_blksum[1024];
__device__ int   g_csrsrc[MAXE];
__device__ float g_csrcoef[MAXE];
__device__ float g_xa[(size_t)MAXN * 128];
__device__ float g_h1[(size_t)MAXN * 256];
__device__ float g_t [(size_t)MAXN * 128];
__device__ float g_z [(size_t)MAXN * 128];
__device__ float g_bnsum[256];
__device__ float g_bnsumsq[256];
__device__ float g_bnsc[256];
__device__ float g_bnsh[256];
__device__ float g_w1t_hi[256 * 128];
__device__ float g_w1t_lo[256 * 128];
__device__ float g_w2t_hi[128 * 256];
__device__ float g_w2t_lo[128 * 256];
__device__ float g_w3t_hi[128 * 128];
__device__ float g_w3t_lo[128 * 128];

// ============================ CSR build ============================
__global__ void hist_kernel(int* __restrict__ cnt, const int* __restrict__ dst, int E) {
    int i = blockIdx.x * blockDim.x + threadIdx.x;
    if (i < E) atomicAdd(&cnt[dst[i]], 1);
}
// exclusive scan part 1 + dinv computation fused
__global__ void ps1_kernel(const int* __restrict__ cnt, int* __restrict__ excl,
                           int* __restrict__ blksum, float* __restrict__ dinv, int N) {
    __shared__ int wsum[8];
    int t = threadIdx.x;
    int i = blockIdx.x * 256 + t;
    int v = (i < N) ? cnt[i] : 0;
    if (i < N) dinv[i] = rsqrtf((float)v + 1.0f);
    int lane = t & 31, wid = t >> 5;
    int x = v;
    #pragma unroll
    for (int o = 1; o < 32; o <<= 1) {
        int y = __shfl_up_sync(0xffffffffu, x, o);
        if (lane >= o) x += y;
    }
    if (lane == 31) wsum[wid] = x;
    __syncthreads();
    if (t == 0) {
        int run = 0;
        #pragma unroll
        for (int w = 0; w < 8; w++) { int tmp = wsum[w]; wsum[w] = run; run += tmp; }
        blksum[blockIdx.x] = run;
    }
    __syncthreads();
    if (i < N) excl[i] = x - v + wsum[wid];
}
__global__ void ps2_kernel(int* __restrict__ blksum, int nb) {
    __shared__ int wsum[16];
    int t = threadIdx.x;
    int v = (t < nb) ? blksum[t] : 0;
    int lane = t & 31, wid = t >> 5;
    int x = v;
    #pragma unroll
    for (int o = 1; o < 32; o <<= 1) {
        int y = __shfl_up_sync(0xffffffffu, x, o);
        if (lane >= o) x += y;
    }
    if (lane == 31) wsum[wid] = x;
    __syncthreads();
    if (t == 0) {
        int run = 0;
        #pragma unroll
        for (int w = 0; w < 16; w++) { int tmp = wsum[w]; wsum[w] = run; run += tmp; }
    }
    __syncthreads();
    if (t < nb) blksum[t] = x - v + wsum[wid];
}
__global__ void ps3_kernel(int* __restrict__ excl, const int* __restrict__ blksum,
                           int* __restrict__ cursor, int N, int E) {
    int i = blockIdx.x * 256 + threadIdx.x;
    if (i < N) {
        int v = excl[i] + blksum[blockIdx.x];
        excl[i] = v;
        cursor[i] = v;
    }
    if (i == 0) excl[N] = E;
}
__global__ void scatter_kernel(const int* __restrict__ src, const int* __restrict__ dst,
                               int* __restrict__ cursor, int* __restrict__ csrc,
                               float* __restrict__ ccoef, const float* __restrict__ dinv, int E) {
    int e = blockIdx.x * blockDim.x + threadIdx.x;
    if (e >= E) return;
    int s = src[e], d = dst[e];
    int pos = atomicAdd(&cursor[d], 1);
    csrc[pos]  = s;
    ccoef[pos] = dinv[s] * dinv[d];
}

// ============================ fused CSR aggregation ============================
template<bool FLN>
__global__ void agg_csr_kernel(const float* __restrict__ feat, float* __restrict__ out,
                               const int* __restrict__ rowstart, const int* __restrict__ csrc,
                               const float* __restrict__ ccoef, const float* __restrict__ dinv,
                               int N, const float* __restrict__ b2,
                               const float* __restrict__ lng, const float* __restrict__ lnb) {
    int w = (blockIdx.x * blockDim.x + threadIdx.x) >> 5;
    int lane = threadIdx.x & 31;
    if (w >= N) return;
    int beg = rowstart[w], end = rowstart[w + 1];
    float4 a0 = make_float4(0.f, 0.f, 0.f, 0.f);
    float4 a1 = make_float4(0.f, 0.f, 0.f, 0.f);
    int idx = beg;
    for (; idx + 1 < end; idx += 2) {
        int s0 = __ldg(&csrc[idx]), s1 = __ldg(&csrc[idx + 1]);
        float c0 = __ldg(&ccoef[idx]), c1 = __ldg(&ccoef[idx + 1]);
        float4 f0 = *(const float4*)(feat + (size_t)s0 * 128 + lane * 4);
        float4 f1 = *(const float4*)(feat + (size_t)s1 * 128 + lane * 4);
        a0.x = fmaf(f0.x, c0, a0.x); a0.y = fmaf(f0.y, c0, a0.y);
        a0.z = fmaf(f0.z, c0, a0.z); a0.w = fmaf(f0.w, c0, a0.w);
        a1.x = fmaf(f1.x, c1, a1.x); a1.y = fmaf(f1.y, c1, a1.y);
        a1.z = fmaf(f1.z, c1, a1.z); a1.w = fmaf(f1.w, c1, a1.w);
    }
    if (idx < end) {
        int s0 = __ldg(&csrc[idx]);
        float c0 = __ldg(&ccoef[idx]);
        float4 f0 = *(const float4*)(feat + (size_t)s0 * 128 + lane * 4);
        a0.x = fmaf(f0.x, c0, a0.x); a0.y = fmaf(f0.y, c0, a0.y);
        a0.z = fmaf(f0.z, c0, a0.z); a0.w = fmaf(f0.w, c0, a0.w);
    }
    float di = dinv[w];
    float c2 = di * di;
    float4 fs = *(const float4*)(feat + (size_t)w * 128 + lane * 4);
    float4 v;
    v.x = fmaf(fs.x, c2, a0.x + a1.x);
    v.y = fmaf(fs.y, c2, a0.y + a1.y);
    v.z = fmaf(fs.z, c2, a0.z + a1.z);
    v.w = fmaf(fs.w, c2, a0.w + a1.w);
    size_t base = (size_t)w * 128 + lane * 4;
    if (!FLN) {
        *(float4*)(out + base) = v;
        return;
    }
    float4 bb = *(const float4*)(b2 + lane * 4);
    v.x += bb.x; v.y += bb.y; v.z += bb.z; v.w += bb.w;
    float s = v.x + v.y + v.z + v.w;
    #pragma unroll
    for (int off = 16; off; off >>= 1) s += __shfl_xor_sync(0xffffffffu, s, off);
    float mu = s * (1.0f / 128.0f);
    float dx = v.x - mu, dy = v.y - mu, dz = v.z - mu, dw = v.w - mu;
    float q = dx * dx + dy * dy + dz * dz + dw * dw;
    #pragma unroll
    for (int off = 16; off; off >>= 1) q += __shfl_xor_sync(0xffffffffu, q, off);
    float rs = rsqrtf(q * (1.0f / 128.0f) + 1e-5f);
    float4 g = *(const float4*)(lng + lane * 4);
    float4 bo = *(const float4*)(lnb + lane * 4);
    float4 o;
    o.x = fmaxf(fmaf(dx * rs, g.x, bo.x), 0.f);
    o.y = fmaxf(fmaf(dy * rs, g.y, bo.y), 0.f);
    o.z = fmaxf(fmaf(dz * rs, g.z, bo.z), 0.f);
    o.w = fmaxf(fmaf(dw * rs, g.w, bo.w), 0.f);
    *(float4*)(out + base) = o;
}

// ============================ misc kernels ============================
// split all 3 weight matrices + zero BN accumulators, one launch
__global__ void wsplit_all_kernel(const float* __restrict__ W1, float* __restrict__ w1h, float* __restrict__ w1l,
                                  const float* __restrict__ W2, float* __restrict__ w2h, float* __restrict__ w2l,
                                  const float* __restrict__ W3, float* __restrict__ w3h, float* __restrict__ w3l,
                                  float* __restrict__ bsum, float* __restrict__ bsq) {
    int i = blockIdx.x * blockDim.x + threadIdx.x;
    if (i < 512) { if (i < 256) bsum[i] = 0.f; else bsq[i - 256] = 0.f; }
    const float* W; float* hiT; float* loT; int K, NOUT, idx;
    if (i < 32768)       { W = W1; hiT = w1h; loT = w1l; K = 128; NOUT = 256; idx = i; }
    else if (i < 65536)  { W = W2; hiT = w2h; loT = w2l; K = 256; NOUT = 128; idx = i - 32768; }
    else if (i < 81920)  { W = W3; hiT = w3h; loT = w3l; K = 128; NOUT = 128; idx = i - 65536; }
    else return;
    int k = idx / NOUT, n = idx % NOUT;
    float x = W[idx];
    float h = tf32rnd(x);
    float l = tf32rnd(x - h);
    hiT[(size_t)n * K + k] = h;
    loT[(size_t)n * K + k] = l;
}
__global__ void colstats_kernel(const float* __restrict__ h, float* __restrict__ sum,
                                float* __restrict__ sumsq, int N) {
    int c = threadIdx.x;
    int r0 = blockIdx.x * 256;
    int r1 = min(r0 + 256, N);
    float s = 0.f, s2 = 0.f;
    for (int r = r0; r < r1; r++) {
        float v = h[(size_t)r * 256 + c];
        s += v;
        s2 = fmaf(v, v, s2);
    }
    atomicAdd(&sum[c], s);
    atomicAdd(&sumsq[c], s2);
}
__global__ void bnfinal_kernel(const float* __restrict__ sum, const float* __restrict__ sumsq,
                               const float* __restrict__ gamma, const float* __restrict__ beta,
                               float* __restrict__ sc, float* __restrict__ sh, int N) {
    int c = threadIdx.x;
    float invN = 1.0f / (float)N;
    float mu = sum[c] * invN;
    float var = fmaxf(sumsq[c] * invN - mu * mu, 0.f);
    float scv = gamma[c] * rsqrtf(var + 1e-5f);
    sc[c] = scv;
    sh[c] = beta[c] - mu * scv;
}
__global__ void decode_kernel(const float* __restrict__ z, const int* __restrict__ ia,
                              const int* __restrict__ ib,
                              const float* __restrict__ cutoff, float* __restrict__ out,
                              int EL, int writeRound) {
    int w = (blockIdx.x * blockDim.x + threadIdx.x) >> 5;
    int lane = threadIdx.x & 31;
    if (w >= EL) return;
    int a = ia[w];
    int b = ib[w];
    float4 za = *(const float4*)(z + (size_t)a * 128 + lane * 4);
    float4 zb = *(const float4*)(z + (size_t)b * 128 + lane * 4);
    float s = za.x * zb.x + za.y * zb.y + za.z * zb.z + za.w * zb.w;
    #pragma unroll
    for (int off = 16; off; off >>= 1) s += __shfl_xor_sync(0xffffffffu, s, off);
    if (lane == 0) {
        out[w] = s;
        if (writeRound) out[(size_t)EL + w] = (s < cutoff[0]) ? 0.0f : 1.0f;
    }
}

// ============================ dual-pipe GEMM ============================
// Row-tiles with (blockIdx.x % 4 == 3) run a SIMT fp32 path (FMA pipe);
// others run the R12 tf32x3 tensor path.  Same outputs, concurrent pipes.
template<int K, bool FUSE, bool HASBIAS>
__global__ void __launch_bounds__(256, 2)
mm_gemm_kernel(const float* __restrict__ A,
               const float* __restrict__ BTh, const float* __restrict__ BTl,
               const float* __restrict__ Borig, int ldB,
               const float* __restrict__ bias,
               const float* __restrict__ sc, const float* __restrict__ sh,
               float* __restrict__ C, int Nrows, int ldC) {
    constexpr int NC  = K / 32;
    constexpr int PAD = 36;
    constexpr int ASZ = 128 * PAD * 4;

    extern __shared__ char smem[];
    int tid = threadIdx.x, lane = tid & 31, warp = tid >> 5;
    int rowBase  = blockIdx.x * 128;
    int colBaseG = blockIdx.y * 128;

    if ((blockIdx.x & 3) != 3) {
        // ================= tensor path (tf32x3, R12-exact) =================
        float* sAh = (float*)(smem);
        float* sAl = (float*)(smem + ASZ);
        float* sBh = (float*)(smem + 2 * ASZ);
        float* sBl = (float*)(smem + 3 * ASZ);
        int warpM = warp & 1, warpN = warp >> 1;

        float acc[4][4][4];
        #pragma unroll
        for (int i = 0; i < 4; i++)
            #pragma unroll
            for (int j = 0; j < 4; j++)
                #pragma unroll
                for (int r = 0; r < 4; r++) acc[i][j][r] = 0.f;

        int larow  = tid >> 1;
        int lkhalf = (tid & 1) * 16;
        bool rOK = (rowBase + larow) < Nrows;
        const float* aRow  = A   + (size_t)(rowBase + larow) * K + lkhalf;
        const float* bRowH = BTh + (size_t)(colBaseG + larow) * K + lkhalf;
        const float* bRowL = BTl + (size_t)(colBaseG + larow) * K + lkhalf;
        float* sAhp = sAh + larow * PAD + lkhalf;
        float* sAlp = sAl + larow * PAD + lkhalf;
        float* sBhp = sBh + larow * PAD + lkhalf;
        float* sBlp = sBl + larow * PAD + lkhalf;

        int al_r = (lane & 7) + (lane & 8);
        int al_k = (lane & 16) >> 2;
        uint32_t aHbase = smem_u32(sAh) + (uint32_t)(((warpM * 64 + al_r) * PAD + al_k) << 2);
        uint32_t aLbase = aHbase + ASZ;
        int bl_n = (lane & 7) + ((lane & 16) >> 1);
        int bl_k = (lane & 8) >> 1;
        uint32_t bHbase = smem_u32(sBh) + (uint32_t)(((warpN * 32 + bl_n) * PAD + bl_k) << 2);
        uint32_t bLbase = bHbase + ASZ;

        for (int c = 0; c < NC; c++) {
            int k0 = c * 32;
            __syncthreads();
            {
                const float4* ap = (const float4*)(aRow + k0);
                #pragma unroll
                for (int j = 0; j < 4; j++) {
                    float4 v = rOK ? ap[j] : make_float4(0.f, 0.f, 0.f, 0.f);
                    if (FUSE) {
                        int kg = k0 + lkhalf + j * 4;
                        float4 s4 = *(const float4*)(sc + kg);
                        float4 h4 = *(const float4*)(sh + kg);
                        v.x = fmaxf(fmaf(v.x, s4.x, h4.x), 0.f);
                        v.y = fmaxf(fmaf(v.y, s4.y, h4.y), 0.f);
                        v.z = fmaxf(fmaf(v.z, s4.z, h4.z), 0.f);
                        v.w = fmaxf(fmaf(v.w, s4.w, h4.w), 0.f);
                    }
                    float4 hi, lo;
                    hi.x = tf32rnd(v.x); lo.x = tf32rnd(v.x - hi.x);
                    hi.y = tf32rnd(v.y); lo.y = tf32rnd(v.y - hi.y);
                    hi.z = tf32rnd(v.z); lo.z = tf32rnd(v.z - hi.z);
                    hi.w = tf32rnd(v.w); lo.w = tf32rnd(v.w - hi.w);
                    *(float4*)(sAhp + j * 4) = hi;
                    *(float4*)(sAlp + j * 4) = lo;
                }
            }
            {
                const float4* bh = (const float4*)(bRowH + k0);
                const float4* bl = (const float4*)(bRowL + k0);
                #pragma unroll
                for (int j = 0; j < 4; j++) *(float4*)(sBhp + j * 4) = bh[j];
                #pragma unroll
                for (int j = 0; j < 4; j++) *(float4*)(sBlp + j * 4) = bl[j];
            }
            __syncthreads();

            #pragma unroll
            for (int s = 0; s < 4; s++) {
                uint32_t koff = (uint32_t)(s * 8 * 4);
                uint32_t bh[2][4], bl[2][4];
                #pragma unroll
                for (int p = 0; p < 2; p++) {
                    uint32_t po = (uint32_t)(p * 16 * PAD * 4);
                    LDSM_X4(bh[p][0], bh[p][1], bh[p][2], bh[p][3], bHbase + po + koff);
                    LDSM_X4(bl[p][0], bl[p][1], bl[p][2], bl[p][3], bLbase + po + koff);
                }
                #pragma unroll
                for (int i = 0; i < 4; i++) {
                    uint32_t io = (uint32_t)(i * 16 * PAD * 4);
                    uint32_t ah0, ah1, ah2, ah3, alo0, alo1, alo2, alo3;
                    LDSM_X4(ah0, ah1, ah2, ah3, aHbase + io + koff);
                    LDSM_X4(alo0, alo1, alo2, alo3, aLbase + io + koff);
                    #pragma unroll
                    for (int j = 0; j < 4; j++) {
                        int p = j >> 1, o = (j & 1) * 2;
                        MMA_TF32(acc[i][j], ah0, ah1, ah2, ah3, bh[p][o], bh[p][o + 1]);
                        MMA_TF32(acc[i][j], ah0, ah1, ah2, ah3, bl[p][o], bl[p][o + 1]);
                        MMA_TF32(acc[i][j], alo0, alo1, alo2, alo3, bh[p][o], bh[p][o + 1]);
                    }
                }
            }
        }

        int gid = lane >> 2, tc2 = (lane & 3) * 2;
        #pragma unroll
        for (int i = 0; i < 4; i++) {
            int r0 = rowBase + warp % 2 * 64 + i * 16 + gid;
            int r1 = r0 + 8;
            #pragma unroll
            for (int j = 0; j < 4; j++) {
                int col = colBaseG + warpN * 32 + j * 8 + tc2;
                float bx = 0.f, by = 0.f;
                if (HASBIAS) { bx = bias[col]; by = bias[col + 1]; }
                if (r0 < Nrows) {
                    float2 v = make_float2(acc[i][j][0] + bx, acc[i][j][1] + by);
                    *(float2*)(C + (size_t)r0 * ldC + col) = v;
                }
                if (r1 < Nrows) {
                    float2 v = make_float2(acc[i][j][2] + bx, acc[i][j][3] + by);
                    *(float2*)(C + (size_t)r1 * ldC + col) = v;
                }
            }
        }
    } else {
        // ================= SIMT fp32 path (FMA pipe; exact) =================
        float* As = (float*)smem;            // [16][132]
        float* Bs = As + 16 * 132;           // [16][128]
        int tx = tid & 15, ty = tid >> 4;
        float acc[8][8];
        #pragma unroll
        for (int i = 0; i < 8; i++)
            #pragma unroll
            for (int j = 0; j < 8; j++) acc[i][j] = 0.f;

        int aR = tid >> 2;
        int aK = (tid & 3) << 2;
        int bK = tid >> 5;
        int bN = (tid & 31) << 2;

        for (int k0 = 0; k0 < K; k0 += 16) {
            #pragma unroll
            for (int i = 0; i < 2; i++) {
                int r = aR + i * 64;
                int grow = rowBase + r;
                float4 v = make_float4(0.f, 0.f, 0.f, 0.f);
                if (grow < Nrows) v = *(const float4*)(A + (size_t)grow * K + k0 + aK);
                if (FUSE) {
                    int kg = k0 + aK;
                    v.x = fmaxf(fmaf(v.x, sc[kg + 0], sh[kg + 0]), 0.f);
                    v.y = fmaxf(fmaf(v.y, sc[kg + 1], sh[kg + 1]), 0.f);
                    v.z = fmaxf(fmaf(v.z, sc[kg + 2], sh[kg + 2]), 0.f);
                    v.w = fmaxf(fmaf(v.w, sc[kg + 3], sh[kg + 3]), 0.f);
                }
                As[(aK + 0) * 132 + r] = v.x; As[(aK + 1) * 132 + r] = v.y;
                As[(aK + 2) * 132 + r] = v.z; As[(aK + 3) * 132 + r] = v.w;
            }
            #pragma unroll
            for (int i = 0; i < 2; i++) {
                int kk = bK + i * 8;
                *(float4*)&Bs[kk * 128 + bN] =
                    *(const float4*)(Borig + (size_t)(k0 + kk) * ldB + colBaseG + bN);
            }
            __syncthreads();
            #pragma unroll
            for (int k = 0; k < 16; k++) {
                float4 a0 = *(float4*)&As[k * 132 + ty * 8];
                float4 a1 = *(float4*)&As[k * 132 + ty * 8 + 4];
                float4 b0 = *(float4*)&Bs[k * 128 + tx * 8];
                float4 b1 = *(float4*)&Bs[k * 128 + tx * 8 + 4];
                float ra[8] = {a0.x, a0.y, a0.z, a0.w, a1.x, a1.y, a1.z, a1.w};
                float rb[8] = {b0.x, b0.y, b0.z, b0.w, b1.x, b1.y, b1.z, b1.w};
                #pragma unroll
                for (int i = 0; i < 8; i++)
                    #pragma unroll
                    for (int j = 0; j < 8; j++)
                        acc[i][j] = fmaf(ra[i], rb[j], acc[i][j]);
            }
            __syncthreads();
        }
        #pragma unroll
        for (int i = 0; i < 8; i++) {
            int grow = rowBase + ty * 8 + i;
            if (grow >= Nrows) break;
            #pragma unroll
            for (int j = 0; j < 8; j += 4) {
                int gcol = colBaseG + tx * 8 + j;
                float4 o;
                o.x = acc[i][j]; o.y = acc[i][j + 1]; o.z = acc[i][j + 2]; o.w = acc[i][j + 3];
                if (HASBIAS) {
                    o.x += bias[gcol]; o.y += bias[gcol + 1];
                    o.z += bias[gcol + 2]; o.w += bias[gcol + 3];
                }
                *(float4*)(C + (size_t)grow * ldC + gcol) = o;
            }
        }
    }
}

// ============================ launch ============================
extern "C" void kernel_launch(void* const* d_in, const int* in_sizes, int n_in,
                              void* d_out, int out_size) {
    const float* x    = (const float*)d_in[0];
    const int*   ei   = (const int*)d_in[1];
    const int*   eli  = (const int*)d_in[2];
    const float* cut  = (const float*)d_in[3];
    const float* W1   = (const float*)d_in[4];
    const float* b1   = (const float*)d_in[5];
    const float* bng  = (const float*)d_in[6];
    const float* bnb  = (const float*)d_in[7];
    const float* W2   = (const float*)d_in[8];
    const float* b2   = (const float*)d_in[9];
    const float* lng  = (const float*)d_in[10];
    const float* lnb  = (const float*)d_in[11];
    const float* linW = (const float*)d_in[12];
    const float* linb = (const float*)d_in[13];

    int N  = in_sizes[0] / 128;
    int E  = in_sizes[1] / 2;
    int EL = in_sizes[2] / 2;
    const int* src = ei;
    const int* dst = ei + E;
    const int* la  = eli;
    const int* lb  = eli + EL;
    float* out = (float*)d_out;

    void* p;
    float *dinv, *xa, *h1, *t, *z, *bsum, *bsq, *bsc, *bsh, *ccoef;
    float *w1h, *w1l, *w2h, *w2l, *w3h, *w3l;
    int *cnt, *rowstart, *cursor, *blksum, *csrc;
    cudaGetSymbolAddress(&p, g_dinv);     dinv = (float*)p;
    cudaGetSymbolAddress(&p, g_cnt);      cnt  = (int*)p;
    cudaGetSymbolAddress(&p, g_rowstart); rowstart = (int*)p;
    cudaGetSymbolAddress(&p, g_cursor);   cursor = (int*)p;
    cudaGetSymbolAddress(&p, g_blksum);   blksum = (int*)p;
    cudaGetSymbolAddress(&p, g_csrsrc);   csrc  = (int*)p;
    cudaGetSymbolAddress(&p, g_csrcoef);  ccoef = (float*)p;
    cudaGetSymbolAddress(&p, g_xa);       xa   = (float*)p;
    cudaGetSymbolAddress(&p, g_h1);       h1   = (float*)p;
    cudaGetSymbolAddress(&p, g_t);        t    = (float*)p;
    cudaGetSymbolAddress(&p, g_z);        z    = (float*)p;
    cudaGetSymbolAddress(&p, g_bnsum);    bsum = (float*)p;
    cudaGetSymbolAddress(&p, g_bnsumsq);  bsq  = (float*)p;
    cudaGetSymbolAddress(&p, g_bnsc);     bsc  = (float*)p;
    cudaGetSymbolAddress(&p, g_bnsh);     bsh  = (float*)p;
    cudaGetSymbolAddress(&p, g_w1t_hi);   w1h  = (float*)p;
    cudaGetSymbolAddress(&p, g_w1t_lo);   w1l  = (float*)p;
    cudaGetSymbolAddress(&p, g_w2t_hi);   w2h  = (float*)p;
    cudaGetSymbolAddress(&p, g_w2t_lo);   w2l  = (float*)p;
    cudaGetSymbolAddress(&p, g_w3t_hi);   w3h  = (float*)p;
    cudaGetSymbolAddress(&p, g_w3t_lo);   w3l  = (float*)p;

    constexpr int SMEMSZ = 4 * 128 * 36 * 4;  // 73728 B, 2 CTAs/SM
    cudaFuncSetAttribute(mm_gemm_kernel<128, false, true>,
                         cudaFuncAttributeMaxDynamicSharedMemorySize, SMEMSZ);
    cudaFuncSetAttribute(mm_gemm_kernel<256, true, false>,
                         cudaFuncAttributeMaxDynamicSharedMemorySize, SMEMSZ);

    cudaMemsetAsync(cnt, 0, (size_t)N * sizeof(int));

    // weight split + BN accumulator zeroing, one launch
    wsplit_all_kernel<<<(81920 + 255) / 256, 256>>>(W1, w1h, w1l, W2, w2h, w2l,
                                                    linW, w3h, w3l, bsum, bsq);

    // ---- CSR build
    int nb = (N + 255) / 256;
    hist_kernel<<<(E + 255) / 256, 256>>>(cnt, dst, E);
    ps1_kernel<<<nb, 256>>>(cnt, rowstart, blksum, dinv, N);
    ps2_kernel<<<1, 512>>>(blksum, nb);
    ps3_kernel<<<nb, 256>>>(rowstart, blksum, cursor, N, E);
    scatter_kernel<<<(E + 255) / 256, 256>>>(src, dst, cursor, csrc, ccoef, dinv, E);

    int tiles = (N + 127) / 128;
    int aggblocks = (N + 7) / 8;

    // layer 1: CSR aggregate -> xa, GEMM1 (+b1)
    agg_csr_kernel<false><<<aggblocks, 256>>>(x, xa, rowstart, csrc, ccoef, dinv, N,
                                              nullptr, nullptr, nullptr);
    mm_gemm_kernel<128, false, true><<<dim3(tiles, 2), 256, SMEMSZ>>>(
        xa, w1h, w1l, W1, 256, b1, nullptr, nullptr, h1, N, 256);

    // BatchNorm stats
    colstats_kernel<<<(N + 255) / 256, 256>>>(h1, bsum, bsq, N);
    bnfinal_kernel<<<1, 256>>>(bsum, bsq, bng, bnb, bsc, bsh, N);

    // layer 2: GEMM2 (fused BN+ReLU on A) -> t, CSR aggregate + b2 + LN + ReLU -> xa
    mm_gemm_kernel<256, true, false><<<dim3(tiles, 1), 256, SMEMSZ>>>(
        h1, w2h, w2l, W2, 128, nullptr, bsc, bsh, t, N, 128);
    agg_csr_kernel<true><<<aggblocks, 256>>>(t, xa, rowstart, csrc, ccoef, dinv, N,
                                             b2, lng, lnb);

    // final linear (+linb)
    mm_gemm_kernel<128, false, true><<<dim3(tiles, 1), 256, SMEMSZ>>>(
        xa, w3h, w3l, linW, 128, linb, nullptr, nullptr, z, N, 128);

    // decode
    int writeRound = (out_size >= 2 * EL) ? 1 : 0;
    decode_kernel<<<((size_t)EL + 7) / 8, 256>>>(z, la, lb, cut, out, EL, writeRound);
}

// round 17
// speedup vs baseline: 1.4315x; 1.1349x over previous
#include <cuda_runtime.h>
#include <cuda_fp16.h>
#include <cstdint>

// ============================ helpers ============================
__device__ __forceinline__ float tf32rnd(float x) {
    uint32_t o; asm("cvt.rna.tf32.f32 %0, %1;" : "=r"(o) : "f"(x)); return __uint_as_float(o);
}
__device__ __forceinline__ uint32_t smem_u32(const void* p) {
    uint32_t a;
    asm("{ .reg .u64 t; cvta.to.shared.u64 t, %1; cvt.u32.u64 %0, t; }" : "=r"(a) : "l"(p));
    return a;
}
#define LDSM_X4(r0, r1, r2, r3, addr) \
    asm volatile("ldmatrix.sync.aligned.m8n8.x4.shared.b16 {%0,%1,%2,%3}, [%4];" \
                 : "=r"(r0), "=r"(r1), "=r"(r2), "=r"(r3) : "r"(addr))
#define MMA_TF32(d, a0, a1, a2, a3, b0, b1) \
    asm volatile("mma.sync.aligned.m16n8k8.row.col.f32.tf32.tf32.f32 " \
                 "{%0,%1,%2,%3},{%4,%5,%6,%7},{%8,%9},{%0,%1,%2,%3};" \
                 : "+f"(d[0]), "+f"(d[1]), "+f"(d[2]), "+f"(d[3]) \
                 : "r"(a0), "r"(a1), "r"(a2), "r"(a3), "r"(b0), "r"(b1))

// ============================ scratch ============================
#define MAXN 100000
#define MAXE 1000000
__device__ float g_dinv[MAXN];
__device__ int   g_cnt[MAXN];
__device__ int   g_rowstart[MAXN + 1];
__device__ int   g_cursor[MAXN];
__device__ int   g_blksum[1024];
__device__ int   g_csrsrc[MAXE];
__device__ float g_csrcoef[MAXE];
__device__ float g_xa[(size_t)MAXN * 128];
__device__ float g_h1[(size_t)MAXN * 256];
__device__ float g_t [(size_t)MAXN * 128];
__device__ float g_z [(size_t)MAXN * 128];
__device__ float g_bnsum[256];
__device__ float g_bnsumsq[256];
__device__ float g_bnsc[256];
__device__ float g_bnsh[256];
__device__ float g_w1t_hi[256 * 128];
__device__ float g_w1t_lo[256 * 128];
__device__ float g_w2t_hi[128 * 256];
__device__ float g_w2t_lo[128 * 256];
__device__ float g_w3t_hi[128 * 128];
__device__ float g_w3t_lo[128 * 128];

// ============================ CSR build ============================
__global__ void hist_kernel(int* __restrict__ cnt, const int* __restrict__ dst, int E) {
    int i = blockIdx.x * blockDim.x + threadIdx.x;
    if (i < E) atomicAdd(&cnt[dst[i]], 1);
}
// exclusive scan part 1 + dinv computation fused
__global__ void ps1_kernel(const int* __restrict__ cnt, int* __restrict__ excl,
                           int* __restrict__ blksum, float* __restrict__ dinv, int N) {
    __shared__ int wsum[8];
    int t = threadIdx.x;
    int i = blockIdx.x * 256 + t;
    int v = (i < N) ? cnt[i] : 0;
    if (i < N) dinv[i] = rsqrtf((float)v + 1.0f);
    int lane = t & 31, wid = t >> 5;
    int x = v;
    #pragma unroll
    for (int o = 1; o < 32; o <<= 1) {
        int y = __shfl_up_sync(0xffffffffu, x, o);
        if (lane >= o) x += y;
    }
    if (lane == 31) wsum[wid] = x;
    __syncthreads();
    if (t == 0) {
        int run = 0;
        #pragma unroll
        for (int w = 0; w < 8; w++) { int tmp = wsum[w]; wsum[w] = run; run += tmp; }
        blksum[blockIdx.x] = run;
    }
    __syncthreads();
    if (i < N) excl[i] = x - v + wsum[wid];
}
__global__ void ps2_kernel(int* __restrict__ blksum, int nb) {
    __shared__ int wsum[16];
    int t = threadIdx.x;
    int v = (t < nb) ? blksum[t] : 0;
    int lane = t & 31, wid = t >> 5;
    int x = v;
    #pragma unroll
    for (int o = 1; o < 32; o <<= 1) {
        int y = __shfl_up_sync(0xffffffffu, x, o);
        if (lane >= o) x += y;
    }
    if (lane == 31) wsum[wid] = x;
    __syncthreads();
    if (t == 0) {
        int run = 0;
        #pragma unroll
        for (int w = 0; w < 16; w++) { int tmp = wsum[w]; wsum[w] = run; run += tmp; }
    }
    __syncthreads();
    if (t < nb) blksum[t] = x - v + wsum[wid];
}
__global__ void ps3_kernel(int* __restrict__ excl, const int* __restrict__ blksum,
                           int* __restrict__ cursor, int N, int E) {
    int i = blockIdx.x * 256 + threadIdx.x;
    if (i < N) {
        int v = excl[i] + blksum[blockIdx.x];
        excl[i] = v;
        cursor[i] = v;
    }
    if (i == 0) excl[N] = E;
}
__global__ void scatter_kernel(const int* __restrict__ src, const int* __restrict__ dst,
                               int* __restrict__ cursor, int* __restrict__ csrc,
                               float* __restrict__ ccoef, const float* __restrict__ dinv, int E) {
    int e = blockIdx.x * blockDim.x + threadIdx.x;
    if (e >= E) return;
    int s = src[e], d = dst[e];
    int pos = atomicAdd(&cursor[d], 1);
    csrc[pos]  = s;
    ccoef[pos] = dinv[s] * dinv[d];
}

// ============================ fused CSR aggregation ============================
template<bool FLN>
__global__ void agg_csr_kernel(const float* __restrict__ feat, float* __restrict__ out,
                               const int* __restrict__ rowstart, const int* __restrict__ csrc,
                               const float* __restrict__ ccoef, const float* __restrict__ dinv,
                               int N, const float* __restrict__ b2,
                               const float* __restrict__ lng, const float* __restrict__ lnb) {
    int w = (blockIdx.x * blockDim.x + threadIdx.x) >> 5;
    int lane = threadIdx.x & 31;
    if (w >= N) return;
    int beg = rowstart[w], end = rowstart[w + 1];
    float4 a0 = make_float4(0.f, 0.f, 0.f, 0.f);
    float4 a1 = make_float4(0.f, 0.f, 0.f, 0.f);
    int idx = beg;
    for (; idx + 1 < end; idx += 2) {
        int s0 = __ldg(&csrc[idx]), s1 = __ldg(&csrc[idx + 1]);
        float c0 = __ldg(&ccoef[idx]), c1 = __ldg(&ccoef[idx + 1]);
        float4 f0 = *(const float4*)(feat + (size_t)s0 * 128 + lane * 4);
        float4 f1 = *(const float4*)(feat + (size_t)s1 * 128 + lane * 4);
        a0.x = fmaf(f0.x, c0, a0.x); a0.y = fmaf(f0.y, c0, a0.y);
        a0.z = fmaf(f0.z, c0, a0.z); a0.w = fmaf(f0.w, c0, a0.w);
        a1.x = fmaf(f1.x, c1, a1.x); a1.y = fmaf(f1.y, c1, a1.y);
        a1.z = fmaf(f1.z, c1, a1.z); a1.w = fmaf(f1.w, c1, a1.w);
    }
    if (idx < end) {
        int s0 = __ldg(&csrc[idx]);
        float c0 = __ldg(&ccoef[idx]);
        float4 f0 = *(const float4*)(feat + (size_t)s0 * 128 + lane * 4);
        a0.x = fmaf(f0.x, c0, a0.x); a0.y = fmaf(f0.y, c0, a0.y);
        a0.z = fmaf(f0.z, c0, a0.z); a0.w = fmaf(f0.w, c0, a0.w);
    }
    float di = dinv[w];
    float c2 = di * di;
    float4 fs = *(const float4*)(feat + (size_t)w * 128 + lane * 4);
    float4 v;
    v.x = fmaf(fs.x, c2, a0.x + a1.x);
    v.y = fmaf(fs.y, c2, a0.y + a1.y);
    v.z = fmaf(fs.z, c2, a0.z + a1.z);
    v.w = fmaf(fs.w, c2, a0.w + a1.w);
    size_t base = (size_t)w * 128 + lane * 4;
    if (!FLN) {
        *(float4*)(out + base) = v;
        return;
    }
    float4 bb = *(const float4*)(b2 + lane * 4);
    v.x += bb.x; v.y += bb.y; v.z += bb.z; v.w += bb.w;
    float s = v.x + v.y + v.z + v.w;
    #pragma unroll
    for (int off = 16; off; off >>= 1) s += __shfl_xor_sync(0xffffffffu, s, off);
    float mu = s * (1.0f / 128.0f);
    float dx = v.x - mu, dy = v.y - mu, dz = v.z - mu, dw = v.w - mu;
    float q = dx * dx + dy * dy + dz * dz + dw * dw;
    #pragma unroll
    for (int off = 16; off; off >>= 1) q += __shfl_xor_sync(0xffffffffu, q, off);
    float rs = rsqrtf(q * (1.0f / 128.0f) + 1e-5f);
    float4 g = *(const float4*)(lng + lane * 4);
    float4 bo = *(const float4*)(lnb + lane * 4);
    float4 o;
    o.x = fmaxf(fmaf(dx * rs, g.x, bo.x), 0.f);
    o.y = fmaxf(fmaf(dy * rs, g.y, bo.y), 0.f);
    o.z = fmaxf(fmaf(dz * rs, g.z, bo.z), 0.f);
    o.w = fmaxf(fmaf(dw * rs, g.w, bo.w), 0.f);
    *(float4*)(out + base) = o;
}

// ============================ misc kernels ============================
// split all 3 weight matrices + zero BN accumulators, one launch
__global__ void wsplit_all_kernel(const float* __restrict__ W1, float* __restrict__ w1h, float* __restrict__ w1l,
                                  const float* __restrict__ W2, float* __restrict__ w2h, float* __restrict__ w2l,
                                  const float* __restrict__ W3, float* __restrict__ w3h, float* __restrict__ w3l,
                                  float* __restrict__ bsum, float* __restrict__ bsq) {
    int i = blockIdx.x * blockDim.x + threadIdx.x;
    if (i < 512) { if (i < 256) bsum[i] = 0.f; else bsq[i - 256] = 0.f; }
    const float* W; float* hiT; float* loT; int K, NOUT, idx;
    if (i < 32768)       { W = W1; hiT = w1h; loT = w1l; K = 128; NOUT = 256; idx = i; }
    else if (i < 65536)  { W = W2; hiT = w2h; loT = w2l; K = 256; NOUT = 128; idx = i - 32768; }
    else if (i < 81920)  { W = W3; hiT = w3h; loT = w3l; K = 128; NOUT = 128; idx = i - 65536; }
    else return;
    int k = idx / NOUT, n = idx % NOUT;
    float x = W[idx];
    float h = tf32rnd(x);
    float l = tf32rnd(x - h);
    hiT[(size_t)n * K + k] = h;
    loT[(size_t)n * K + k] = l;
}
__global__ void colstats_kernel(const float* __restrict__ h, float* __restrict__ sum,
                                float* __restrict__ sumsq, int N) {
    int c = threadIdx.x;
    int r0 = blockIdx.x * 256;
    int r1 = min(r0 + 256, N);
    float s = 0.f, s2 = 0.f;
    for (int r = r0; r < r1; r++) {
        float v = h[(size_t)r * 256 + c];
        s += v;
        s2 = fmaf(v, v, s2);
    }
    atomicAdd(&sum[c], s);
    atomicAdd(&sumsq[c], s2);
}
__global__ void bnfinal_kernel(const float* __restrict__ sum, const float* __restrict__ sumsq,
                               const float* __restrict__ gamma, const float* __restrict__ beta,
                               float* __restrict__ sc, float* __restrict__ sh, int N) {
    int c = threadIdx.x;
    float invN = 1.0f / (float)N;
    float mu = sum[c] * invN;
    float var = fmaxf(sumsq[c] * invN - mu * mu, 0.f);
    float scv = gamma[c] * rsqrtf(var + 1e-5f);
    sc[c] = scv;
    sh[c] = beta[c] - mu * scv;
}
__global__ void decode_kernel(const float* __restrict__ z, const int* __restrict__ ia,
                              const int* __restrict__ ib,
                              const float* __restrict__ cutoff, float* __restrict__ out,
                              int EL, int writeRound) {
    int w = (blockIdx.x * blockDim.x + threadIdx.x) >> 5;
    int lane = threadIdx.x & 31;
    if (w >= EL) return;
    int a = ia[w];
    int b = ib[w];
    float4 za = *(const float4*)(z + (size_t)a * 128 + lane * 4);
    float4 zb = *(const float4*)(z + (size_t)b * 128 + lane * 4);
    float s = za.x * zb.x + za.y * zb.y + za.z * zb.z + za.w * zb.w;
    #pragma unroll
    for (int off = 16; off; off >>= 1) s += __shfl_xor_sync(0xffffffffu, s, off);
    if (lane == 0) {
        out[w] = s;
        if (writeRound) out[(size_t)EL + w] = (s < cutoff[0]) ? 0.0f : 1.0f;
    }
}

// ============================ mma.sync tf32x3 GEMM (R12-exact) ============================
template<int K, bool FUSE, bool HASBIAS>
__global__ void __launch_bounds__(256, 2)
mm_gemm_kernel(const float* __restrict__ A,
               const float* __restrict__ BTh, const float* __restrict__ BTl,
               const float* __restrict__ bias,
               const float* __restrict__ sc, const float* __restrict__ sh,
               float* __restrict__ C, int Nrows, int ldC) {
    constexpr int NC  = K / 32;
    constexpr int PAD = 36;
    constexpr int ASZ = 128 * PAD * 4;

    extern __shared__ char smem[];
    float* sAh = (float*)(smem);
    float* sAl = (float*)(smem + ASZ);
    float* sBh = (float*)(smem + 2 * ASZ);
    float* sBl = (float*)(smem + 3 * ASZ);

    int tid = threadIdx.x, lane = tid & 31, warp = tid >> 5;
    int warpM = warp & 1, warpN = warp >> 1;
    int rowBase  = blockIdx.x * 128;
    int colBaseG = blockIdx.y * 128;

    float acc[4][4][4];
    #pragma unroll
    for (int i = 0; i < 4; i++)
        #pragma unroll
        for (int j = 0; j < 4; j++)
            #pragma unroll
            for (int r = 0; r < 4; r++) acc[i][j][r] = 0.f;

    int larow  = tid >> 1;
    int lkhalf = (tid & 1) * 16;
    bool rOK = (rowBase + larow) < Nrows;
    const float* aRow  = A   + (size_t)(rowBase + larow) * K + lkhalf;
    const float* bRowH = BTh + (size_t)(colBaseG + larow) * K + lkhalf;
    const float* bRowL = BTl + (size_t)(colBaseG + larow) * K + lkhalf;
    float* sAhp = sAh + larow * PAD + lkhalf;
    float* sAlp = sAl + larow * PAD + lkhalf;
    float* sBhp = sBh + larow * PAD + lkhalf;
    float* sBlp = sBl + larow * PAD + lkhalf;

    int al_r = (lane & 7) + (lane & 8);
    int al_k = (lane & 16) >> 2;
    uint32_t aHbase = smem_u32(sAh) + (uint32_t)(((warpM * 64 + al_r) * PAD + al_k) << 2);
    uint32_t aLbase = aHbase + ASZ;
    int bl_n = (lane & 7) + ((lane & 16) >> 1);
    int bl_k = (lane & 8) >> 1;
    uint32_t bHbase = smem_u32(sBh) + (uint32_t)(((warpN * 32 + bl_n) * PAD + bl_k) << 2);
    uint32_t bLbase = bHbase + ASZ;

    for (int c = 0; c < NC; c++) {
        int k0 = c * 32;
        __syncthreads();
        {
            const float4* ap = (const float4*)(aRow + k0);
            #pragma unroll
            for (int j = 0; j < 4; j++) {
                float4 v = rOK ? ap[j] : make_float4(0.f, 0.f, 0.f, 0.f);
                if (FUSE) {
                    int kg = k0 + lkhalf + j * 4;
                    float4 s4 = *(const float4*)(sc + kg);
                    float4 h4 = *(const float4*)(sh + kg);
                    v.x = fmaxf(fmaf(v.x, s4.x, h4.x), 0.f);
                    v.y = fmaxf(fmaf(v.y, s4.y, h4.y), 0.f);
                    v.z = fmaxf(fmaf(v.z, s4.z, h4.z), 0.f);
                    v.w = fmaxf(fmaf(v.w, s4.w, h4.w), 0.f);
                }
                float4 hi, lo;
                hi.x = tf32rnd(v.x); lo.x = tf32rnd(v.x - hi.x);
                hi.y = tf32rnd(v.y); lo.y = tf32rnd(v.y - hi.y);
                hi.z = tf32rnd(v.z); lo.z = tf32rnd(v.z - hi.z);
                hi.w = tf32rnd(v.w); lo.w = tf32rnd(v.w - hi.w);
                *(float4*)(sAhp + j * 4) = hi;
                *(float4*)(sAlp + j * 4) = lo;
            }
        }
        {
            const float4* bh = (const float4*)(bRowH + k0);
            const float4* bl = (const float4*)(bRowL + k0);
            #pragma unroll
            for (int j = 0; j < 4; j++) *(float4*)(sBhp + j * 4) = bh[j];
            #pragma unroll
            for (int j = 0; j < 4; j++) *(float4*)(sBlp + j * 4) = bl[j];
        }
        __syncthreads();

        #pragma unroll
        for (int s = 0; s < 4; s++) {
            uint32_t koff = (uint32_t)(s * 8 * 4);
            uint32_t bh[2][4], bl[2][4];
            #pragma unroll
            for (int p = 0; p < 2; p++) {
                uint32_t po = (uint32_t)(p * 16 * PAD * 4);
                LDSM_X4(bh[p][0], bh[p][1], bh[p][2], bh[p][3], bHbase + po + koff);
                LDSM_X4(bl[p][0], bl[p][1], bl[p][2], bl[p][3], bLbase + po + koff);
            }
            #pragma unroll
            for (int i = 0; i < 4; i++) {
                uint32_t io = (uint32_t)(i * 16 * PAD * 4);
                uint32_t ah0, ah1, ah2, ah3, alo0, alo1, alo2, alo3;
                LDSM_X4(ah0, ah1, ah2, ah3, aHbase + io + koff);
                LDSM_X4(alo0, alo1, alo2, alo3, aLbase + io + koff);
                #pragma unroll
                for (int j = 0; j < 4; j++) {
                    int p = j >> 1, o = (j & 1) * 2;
                    MMA_TF32(acc[i][j], ah0, ah1, ah2, ah3, bh[p][o], bh[p][o + 1]);
                    MMA_TF32(acc[i][j], ah0, ah1, ah2, ah3, bl[p][o], bl[p][o + 1]);
                    MMA_TF32(acc[i][j], alo0, alo1, alo2, alo3, bh[p][o], bh[p][o + 1]);
                }
            }
        }
    }

    int gid = lane >> 2, tc2 = (lane & 3) * 2;
    #pragma unroll
    for (int i = 0; i < 4; i++) {
        int r0 = rowBase + warpM * 64 + i * 16 + gid;
        int r1 = r0 + 8;
        #pragma unroll
        for (int j = 0; j < 4; j++) {
            int col = colBaseG + warpN * 32 + j * 8 + tc2;
            float bx = 0.f, by = 0.f;
            if (HASBIAS) { bx = bias[col]; by = bias[col + 1]; }
            if (r0 < Nrows) {
                float2 v = make_float2(acc[i][j][0] + bx, acc[i][j][1] + by);
                *(float2*)(C + (size_t)r0 * ldC + col) = v;
            }
            if (r1 < Nrows) {
                float2 v = make_float2(acc[i][j][2] + bx, acc[i][j][3] + by);
                *(float2*)(C + (size_t)r1 * ldC + col) = v;
            }
        }
    }
}

// ============================ launch ============================
extern "C" void kernel_launch(void* const* d_in, const int* in_sizes, int n_in,
                              void* d_out, int out_size) {
    const float* x    = (const float*)d_in[0];
    const int*   ei   = (const int*)d_in[1];
    const int*   eli  = (const int*)d_in[2];
    const float* cut  = (const float*)d_in[3];
    const float* W1   = (const float*)d_in[4];
    const float* b1   = (const float*)d_in[5];
    const float* bng  = (const float*)d_in[6];
    const float* bnb  = (const float*)d_in[7];
    const float* W2   = (const float*)d_in[8];
    const float* b2   = (const float*)d_in[9];
    const float* lng  = (const float*)d_in[10];
    const float* lnb  = (const float*)d_in[11];
    const float* linW = (const float*)d_in[12];
    const float* linb = (const float*)d_in[13];

    int N  = in_sizes[0] / 128;
    int E  = in_sizes[1] / 2;
    int EL = in_sizes[2] / 2;
    const int* src = ei;
    const int* dst = ei + E;
    const int* la  = eli;
    const int* lb  = eli + EL;
    float* out = (float*)d_out;

    void* p;
    float *dinv, *xa, *h1, *t, *z, *bsum, *bsq, *bsc, *bsh, *ccoef;
    float *w1h, *w1l, *w2h, *w2l, *w3h, *w3l;
    int *cnt, *rowstart, *cursor, *blksum, *csrc;
    cudaGetSymbolAddress(&p, g_dinv);     dinv = (float*)p;
    cudaGetSymbolAddress(&p, g_cnt);      cnt  = (int*)p;
    cudaGetSymbolAddress(&p, g_rowstart); rowstart = (int*)p;
    cudaGetSymbolAddress(&p, g_cursor);   cursor = (int*)p;
    cudaGetSymbolAddress(&p, g_blksum);   blksum = (int*)p;
    cudaGetSymbolAddress(&p, g_csrsrc);   csrc  = (int*)p;
    cudaGetSymbolAddress(&p, g_csrcoef);  ccoef = (float*)p;
    cudaGetSymbolAddress(&p, g_xa);       xa   = (float*)p;
    cudaGetSymbolAddress(&p, g_h1);       h1   = (float*)p;
    cudaGetSymbolAddress(&p, g_t);        t    = (float*)p;
    cudaGetSymbolAddress(&p, g_z);        z    = (float*)p;
    cudaGetSymbolAddress(&p, g_bnsum);    bsum = (float*)p;
    cudaGetSymbolAddress(&p, g_bnsumsq);  bsq  = (float*)p;
    cudaGetSymbolAddress(&p, g_bnsc);     bsc  = (float*)p;
    cudaGetSymbolAddress(&p, g_bnsh);     bsh  = (float*)p;
    cudaGetSymbolAddress(&p, g_w1t_hi);   w1h  = (float*)p;
    cudaGetSymbolAddress(&p, g_w1t_lo);   w1l  = (float*)p;
    cudaGetSymbolAddress(&p, g_w2t_hi);   w2h  = (float*)p;
    cudaGetSymbolAddress(&p, g_w2t_lo);   w2l  = (float*)p;
    cudaGetSymbolAddress(&p, g_w3t_hi);   w3h  = (float*)p;
    cudaGetSymbolAddress(&p, g_w3t_lo);   w3l  = (float*)p;

    constexpr int SMEMSZ = 4 * 128 * 36 * 4;  // 73728 B, 2 CTAs/SM
    cudaFuncSetAttribute(mm_gemm_kernel<128, false, true>,
                         cudaFuncAttributeMaxDynamicSharedMemorySize, SMEMSZ);
    cudaFuncSetAttribute(mm_gemm_kernel<256, true, false>,
                         cudaFuncAttributeMaxDynamicSharedMemorySize, SMEMSZ);

    cudaMemsetAsync(cnt, 0, (size_t)N * sizeof(int));

    // weight split + BN accumulator zeroing, one launch
    wsplit_all_kernel<<<(81920 + 255) / 256, 256>>>(W1, w1h, w1l, W2, w2h, w2l,
                                                    linW, w3h, w3l, bsum, bsq);

    // ---- CSR build
    int nb = (N + 255) / 256;
    hist_kernel<<<(E + 255) / 256, 256>>>(cnt, dst, E);
    ps1_kernel<<<nb, 256>>>(cnt, rowstart, blksum, dinv, N);
    ps2_kernel<<<1, 512>>>(blksum, nb);
    ps3_kernel<<<nb, 256>>>(rowstart, blksum, cursor, N, E);
    scatter_kernel<<<(E + 255) / 256, 256>>>(src, dst, cursor, csrc, ccoef, dinv, E);

    int tiles = (N + 127) / 128;
    int aggblocks = (N + 7) / 8;

    // layer 1: CSR aggregate -> xa, GEMM1 (+b1)
    agg_csr_kernel<false><<<aggblocks, 256>>>(x, xa, rowstart, csrc, ccoef, dinv, N,
                                              nullptr, nullptr, nullptr);
    mm_gemm_kernel<128, false, true><<<dim3(tiles, 2), 256, SMEMSZ>>>(
        xa, w1h, w1l, b1, nullptr, nullptr, h1, N, 256);

    // BatchNorm stats
    colstats_kernel<<<(N + 255) / 256, 256>>>(h1, bsum, bsq, N);
    bnfinal_kernel<<<1, 256>>>(bsum, bsq, bng, bnb, bsc, bsh, N);

    // layer 2: GEMM2 (fused BN+ReLU on A) -> t, CSR aggregate + b2 + LN + ReLU -> xa
    mm_gemm_kernel<256, true, false><<<dim3(tiles, 1), 256, SMEMSZ>>>(
        h1, w2h, w2l, nullptr, bsc, bsh, t, N, 128);
    agg_csr_kernel<true><<<aggblocks, 256>>>(t, xa, rowstart, csrc, ccoef, dinv, N,
                                             b2, lng, lnb);

    // final linear (+linb)
    mm_gemm_kernel<128, false, true><<<dim3(tiles, 1), 256, SMEMSZ>>>(
        xa, w3h, w3l, linb, nullptr, nullptr, z, N, 128);

    // decode
    int writeRound = (out_size >= 2 * EL) ? 1 : 0;
    decode_kernel<<<((size_t)EL + 7) / 8, 256>>>(z, la, lb, cut, out, EL, writeRound);
}